// round 11
// baseline (speedup 1.0000x reference)
#include <cuda_runtime.h>
#include <math.h>

#define B 128
#define C 6
#define H 224
#define W 224
#define HWSZ (H*W)          // 50176
#define HW4 (HWSZ/4)        // 12544 float4 per channel
#define POOL 7
#define NS (POOL*POOL)      // 49
#define BC (B*C)            // 768
#define CS (C*NS)           // 294
#define FEAT (3*C)          // 18
#define W4 (W/4)            // 56 float4 per row

__device__ float g_pooled[BC * NS];
__device__ int   g_cnt[B];

__constant__ float c_prior[36] = {
    1.0f,  0.0f,  0.6f,  0.0f, -2.0f, 0.0f,
    0.0f,  1.0f,  0.6f,  0.0f,  0.0f, 0.0f,
    0.1f,  0.1f,  0.5f,  0.0f,  0.0f, 0.0f,
    0.0f,  0.0f,  0.0f,  1.0f,  0.0f, 0.0f,
    0.0f,  0.0f,  0.0f,  0.0f,  1.0f, 0.2f,
    0.0f, -0.6f, -0.6f, -0.6f,  0.6f, 1.0f
};
__constant__ float c_sign[6] = {1.f, -1.f, 1.f, -1.f, 1.f, 1.f};

__device__ __forceinline__ float tanh_f(float x) {
    float y;
    asm("tanh.approx.f32 %0, %1;" : "=f"(y) : "f"(x));
    return y;
}

__global__ void zero_cnt_kernel() {
    if (threadIdx.x < B) g_cnt[threadIdx.x] = 0;
}

__device__ __forceinline__ void load_window(
    float4* dst, const float* __restrict__ xc, int win, int sub, int c4)
{
    const int py = win / POOL, px = win - py * POOL;
    const float4* __restrict__ base =
        (const float4*)(xc + (py * 32 + sub) * W + px * 32) + c4;
    #pragma unroll
    for (int r = 0; r < 8; ++r) dst[r] = base[r * W];  // rows sub, sub+4, ...
}

// ---------------------------------------------------------------------------
// One fused kernel. Block = (batch b, concept d). Phases:
//  1. stats: stream own 200KB channel (fp32 sum/sumsq)
//  2. windows: gate (tanh) + 32x32 pool, L2 re-read, depth-2 window prefetch
//  3. publish pooled -> fence -> atomicAdd(cnt[b]); spin until cnt[b]==6
//  4. graph mixing + features + bilinear upsample (DRAM writes overlap other
//     blocks' phase-1/2 reads chip-wide)
// 40KB dynamic smem pad pins occupancy at 3-4/SM: L2 re-read footprint fits,
// and >=3 resident blocks guarantee spin progress (siblings within +5).
// ---------------------------------------------------------------------------
__global__ __launch_bounds__(256, 3)
void fused_kernel(const float* __restrict__ x,
                  const float* __restrict__ P_delta,
                  float* __restrict__ feat_out,
                  float* __restrict__ out)
{
    extern __shared__ float smem_pad[];            // occupancy control (unused)
    __shared__ float ra[8], rb[8];
    __shared__ float s_sc, s_of;
    __shared__ float xs[CS], sal[CS], tmp[NS];
    __shared__ float Pcol[C], smean[C];
    __shared__ __align__(16) float g[52];
    __shared__ __align__(16) float4 hr4[POOL * W4];

    const int bc = blockIdx.x;
    const int b = bc / C, d = bc - b * C;
    const int tid = threadIdx.x;
    const int warp = tid >> 5, lane = tid & 31;
    const float* __restrict__ xc = x + (size_t)bc * HWSZ;
    if (tid > 100000) smem_pad[0] = 0.f;           // keep pad alive

    // ---- phase 1: stats (49 float4 per thread, batches of 8) ----
    {
        const float4* __restrict__ xin = (const float4*)xc;
        float sum = 0.f, sq = 0.f;
        #pragma unroll
        for (int base = 0; base < 48; base += 8) {
            float4 v[8];
            #pragma unroll
            for (int k = 0; k < 8; ++k) v[k] = xin[(base + k) * 256 + tid];
            #pragma unroll
            for (int k = 0; k < 8; ++k) {
                sum += (v[k].x + v[k].y) + (v[k].z + v[k].w);
                sq  += fmaf(v[k].x, v[k].x, fmaf(v[k].y, v[k].y,
                       fmaf(v[k].z, v[k].z, v[k].w * v[k].w)));
            }
        }
        {
            float4 v = xin[48 * 256 + tid];
            sum += (v.x + v.y) + (v.z + v.w);
            sq  += fmaf(v.x, v.x, fmaf(v.y, v.y, fmaf(v.z, v.z, v.w * v.w)));
        }
        #pragma unroll
        for (int o = 16; o; o >>= 1) {
            sum += __shfl_down_sync(0xffffffffu, sum, o);
            sq  += __shfl_down_sync(0xffffffffu, sq,  o);
        }
        if (lane == 0) { ra[warp] = sum; rb[warp] = sq; }
        __syncthreads();
        if (warp == 0) {
            float s = (lane < 8) ? ra[lane] : 0.f;
            float q = (lane < 8) ? rb[lane] : 0.f;
            #pragma unroll
            for (int o = 4; o; o >>= 1) {
                s += __shfl_down_sync(0xffffffffu, s, o);
                q += __shfl_down_sync(0xffffffffu, q, o);
            }
            if (lane == 0) {
                const float invN = 1.0f / (float)HWSZ;
                float mean = s * invN;
                float var = fmaxf((q - s * s * invN)
                                  * (1.0f / (float)(HWSZ - 1)), 0.f);
                float is = 1.0f / (sqrtf(var) + 1e-5f);
                s_sc = is; s_of = -mean * is;
            }
        }
        __syncthreads();
    }
    const float sc = s_sc, of = s_of;

    // ---- phase 2: windows (8 warps, depth-2 prefetch pipeline) ----
    {
        const int sub = lane >> 3, c4 = lane & 7;
        float4 cur[8], nxt[8];
        load_window(cur, xc, warp, sub, c4);
        for (int win = warp; win < NS; win += 8) {
            if (win + 8 < NS) load_window(nxt, xc, win + 8, sub, c4);
            float acc = 0.f;
            #pragma unroll
            for (int r = 0; r < 8; ++r) {
                acc += tanh_f(fmaf(cur[r].x, sc, of));
                acc += tanh_f(fmaf(cur[r].y, sc, of));
                acc += tanh_f(fmaf(cur[r].z, sc, of));
                acc += tanh_f(fmaf(cur[r].w, sc, of));
            }
            #pragma unroll
            for (int o = 16; o; o >>= 1)
                acc += __shfl_down_sync(0xffffffffu, acc, o);
            if (lane == 0)
                g_pooled[bc * NS + win] = acc * (1.0f / 2048.0f) + 0.5f;
            #pragma unroll
            for (int r = 0; r < 8; ++r) cur[r] = nxt[r];
        }
    }
    __syncthreads();

    // ---- phase 3: publish + spin on batch counter ----
    if (tid == 0) {
        __threadfence();
        atomicAdd(&g_cnt[b], 1);
        while (atomicAdd(&g_cnt[b], 0) < C) __nanosleep(256);
    }
    __syncthreads();
    __threadfence();

    // ---- phase 4a: mixing ----
    for (int i = tid; i < CS; i += 256) xs[i] = __ldcg(&g_pooled[b * CS + i]);
    if (tid < C) Pcol[tid] = c_prior[tid * 6 + d] + 0.2f * tanhf(P_delta[tid * 6 + d]);
    __syncthreads();

    if (tid < C) {
        float m = 0.f;
        #pragma unroll
        for (int s = 0; s < NS; ++s) m += xs[tid * NS + s];
        smean[tid] = m * (1.0f / (float)NS);
    }
    __syncthreads();

    for (int i = tid; i < CS; i += 256) {
        const int cc = i / NS;
        sal[i] = fmaxf(c_sign[cc] * (xs[i] - smean[cc]), 0.0f);
    }
    __syncthreads();

    if (tid < NS) {
        tmp[tid] = sal[tid]        * Pcol[0] + sal[NS + tid]   * Pcol[1]
                 + sal[2*NS + tid] * Pcol[2] + sal[3*NS + tid] * Pcol[3]
                 + sal[4*NS + tid] * Pcol[4] + sal[5*NS + tid] * Pcol[5];
    }
    __syncthreads();

    if (tid < NS) {
        const int ty = tid / POOL, tx = tid - ty * POOL;
        float acc = 0.f;
        int s = 0;
        #pragma unroll
        for (int sy = 0; sy < POOL; ++sy) {
            const float dy2 = (float)((sy - ty) * (sy - ty));
            #pragma unroll
            for (int sx = 0; sx < POOL; ++sx, ++s) {
                const float dx = (float)(sx - tx);
                acc += __expf(-(dy2 + dx * dx) * 0.78125f) * tmp[s];
            }
        }
        g[tid] = c_sign[d] * fmaxf(acc, 0.0f);
    }
    __syncthreads();

    // ---- phase 4b: features ----
    if (tid < 32) {
        float a  = g[tid];
        bool hi  = (tid + 32) < NS;
        float b2 = hi ? g[tid + 32] : 0.f;
        float s  = a + b2;
        float mx = hi ? fmaxf(a, b2) : a;
        float mn = hi ? fminf(a, b2) : a;
        #pragma unroll
        for (int o = 16; o; o >>= 1) {
            s  += __shfl_down_sync(0xffffffffu, s,  o);
            mx  = fmaxf(mx, __shfl_down_sync(0xffffffffu, mx, o));
            mn  = fminf(mn, __shfl_down_sync(0xffffffffu, mn, o));
        }
        if (tid == 0) {
            feat_out[b * FEAT + d]         = s * (1.0f / (float)NS);
            feat_out[b * FEAT + C + d]     = mx;
            feat_out[b * FEAT + 2 * C + d] = mn;
        }
    }

    // ---- phase 4c: horizontal interpolation table ----
    {
        float* hrows = (float*)hr4;
        for (int i = tid; i < POOL * W; i += 256) {
            const int r = i / W, j = i - r * W;
            const float sx = (j + 0.5f) * (1.0f / 32.0f) - 0.5f;
            const float x0f = floorf(sx);
            const float fx = sx - x0f;
            const int x0 = max(0, min(6, (int)x0f));
            const int x1 = max(0, min(6, (int)x0f + 1));
            const float a = g[r * POOL + x0];
            hrows[r * W + j] = a + fx * (g[r * POOL + x1] - a);
        }
    }
    __syncthreads();

    // ---- phase 4d: vertical pass + streaming stores (448 items / 256 thr) ----
    float4* __restrict__ obase = (float4*)(out + (size_t)bc * HWSZ);
    for (int it = tid; it < 448; it += 256) {
        const int s  = it / W4;          // 0..7 row segment
        const int c4 = it - s * W4;      // 0..55
        const bool edge = (s == 0) | (s == 7);
        const int y0 = (s == 0) ? 0 : (s - 1);
        const int y1 = (s == 7) ? 6 : s;
        const int row0 = (s == 0) ? 0 : (32 * s - 16);
        const int n = edge ? 16 : 32;

        const float4 a  = hr4[y0 * W4 + c4];
        const float4 bb = hr4[y1 * W4 + c4];
        const float dxv = bb.x - a.x, dyv = bb.y - a.y;
        const float dzv = bb.z - a.z, dwv = bb.w - a.w;

        float4* __restrict__ o = obase + row0 * W4 + c4;
        #pragma unroll
        for (int r = 0; r < 32; ++r) {
            if (r < n) {
                const float fy = 0.015625f + (float)r * 0.03125f;
                float4 vv;
                vv.x = fmaf(fy, dxv, a.x);
                vv.y = fmaf(fy, dyv, a.y);
                vv.z = fmaf(fy, dzv, a.z);
                vv.w = fmaf(fy, dwv, a.w);
                __stcs(&o[r * W4], vv);
            }
        }
    }
}

// ---------------------------------------------------------------------------
extern "C" void kernel_launch(void* const* d_in, const int* in_sizes, int n_in,
                              void* d_out, int out_size)
{
    const float* x       = (const float*)d_in[0];   // (128,6,224,224) f32
    const float* P_delta = (const float*)d_in[1];   // (6,6) f32
    float* out = (float*)d_out;                     // [B*18 | B*C*H*W]

    const int PAD = 40 * 1024;    // dynamic smem pad -> occupancy 3-4/SM
    cudaFuncSetAttribute(fused_kernel,
                         cudaFuncAttributeMaxDynamicSharedMemorySize, PAD);

    zero_cnt_kernel<<<1, 128>>>();
    fused_kernel<<<BC, 256, PAD>>>(x, P_delta, out, out + (size_t)B * FEAT);
}